// round 2
// baseline (speedup 1.0000x reference)
#include <cuda_runtime.h>
#include <stdint.h>

#define NN 100000
#define EE 1600000
#define F_IN 128
#define F_H 64
#define F_OUT 32

// ---------------- device scratch (no allocations allowed) ----------------
__device__ int   g_is64;
__device__ int   g_deg[NN];
__device__ float g_dinv[NN];
__device__ float g_g1[NN * F_H];
__device__ float g_acc1[NN * F_H];
__device__ float g_g2[NN * F_OUT];
__device__ float g_acc2[NN * F_OUT];

// ---------------- dtype detection for edge_index ----------------
// If data is int64: every u64 word is a node id < NN.
// If data is int32: u64 combines two ids; high word is a random id,
// nonzero w.p. 1-1e-5 per entry -> over 64 entries detection is certain.
__global__ void k_detect(const unsigned long long* __restrict__ idx) {
    if (blockIdx.x == 0 && threadIdx.x == 0) {
        int is64 = 1;
        for (int i = 0; i < 64; i++) {
            if (idx[i] >= (unsigned long long)NN) { is64 = 0; break; }
        }
        g_is64 = is64;
    }
}

__global__ void k_init_deg(int n) {
    int i = blockIdx.x * blockDim.x + threadIdx.x;
    if (i < n) g_deg[i] = 1;   // self-loop
}

__global__ void k_deg(const void* __restrict__ idxp, int E) {
    int e = blockIdx.x * blockDim.x + threadIdx.x;
    if (e >= E) return;
    int dst;
    if (g_is64) dst = (int)((const long long*)idxp)[E + e];
    else        dst = ((const int*)idxp)[E + e];
    atomicAdd(&g_deg[dst], 1);
}

__global__ void k_dinv(int n) {
    int i = blockIdx.x * blockDim.x + threadIdx.x;
    if (i < n) g_dinv[i] = rsqrtf((float)g_deg[i]);
}

// ---------------- GEMM1: g1[i][j] = dinv[i] * dot(x[i,:], W1[j,:]) ----------------
// 256 threads = 8 warps, each warp does one row. W1 transposed in smem.
__global__ void __launch_bounds__(256) k_gemm1(const float* __restrict__ x,
                                               const float* __restrict__ W1, int n) {
    __shared__ float W1t[F_IN * F_H];   // [k][j]
    __shared__ float xs[8][F_IN];
    int tid = threadIdx.x;
    for (int t = tid; t < F_IN * F_H; t += 256) {
        int j = t / F_IN, k = t % F_IN;   // coalesced read of W1[j*128+k]
        W1t[k * F_H + j] = W1[t];
    }
    __syncthreads();
    int w = tid >> 5, lane = tid & 31;
    int row = blockIdx.x * 8 + w;
    if (row < n) {
        ((float4*)xs[w])[lane] = ((const float4*)(x + (size_t)row * F_IN))[lane];
    }
    __syncwarp();
    if (row >= n) return;

    float a0 = 0.f, a1 = 0.f;
    const float* xr = xs[w];
    #pragma unroll
    for (int k = 0; k < F_IN; k += 4) {
        float4 xk = *(const float4*)(xr + k);
        float2 w0 = *(const float2*)(W1t + (k + 0) * F_H + 2 * lane);
        float2 w1 = *(const float2*)(W1t + (k + 1) * F_H + 2 * lane);
        float2 w2 = *(const float2*)(W1t + (k + 2) * F_H + 2 * lane);
        float2 w3 = *(const float2*)(W1t + (k + 3) * F_H + 2 * lane);
        a0 += xk.x * w0.x + xk.y * w1.x + xk.z * w2.x + xk.w * w3.x;
        a1 += xk.x * w0.y + xk.y * w1.y + xk.z * w2.y + xk.w * w3.y;
    }
    float di = g_dinv[row];
    float2 o = make_float2(a0 * di, a1 * di);
    *(float2*)(g_g1   + (size_t)row * F_H + 2 * lane) = o;
    *(float2*)(g_acc1 + (size_t)row * F_H + 2 * lane) = o;
}

// ---------------- scatter layer 1: acc1[dst] += g1[src], 16 threads/edge ----------------
__global__ void __launch_bounds__(256) k_scatter1(const void* __restrict__ idxp, int E) {
    long long g = (long long)blockIdx.x * blockDim.x + threadIdx.x;
    if (g >= (long long)E * 16) return;
    int e = (int)(g >> 4);
    int c = (int)(g & 15);
    int src, dst;
    if (g_is64) {
        const long long* I = (const long long*)idxp;
        src = (int)I[e]; dst = (int)I[E + e];
    } else {
        const int* I = (const int*)idxp;
        src = I[e]; dst = I[E + e];
    }
    float4 v = ((const float4*)g_g1)[(size_t)src * 16 + c];
    float* a = (float*)(((float4*)g_acc1) + (size_t)dst * 16 + c);
    asm volatile("red.global.add.v4.f32 [%0], {%1,%2,%3,%4};"
                 :: "l"(a), "f"(v.x), "f"(v.y), "f"(v.z), "f"(v.w) : "memory");
}

// ---------------- fused: finalize1 + ReLU + GEMM2 + init acc2 ----------------
// r[j] = relu(dinv[i]*acc1[i][j] + b1[j]);  g2[i][m] = dinv[i] * dot(r, W2[m,:])
__global__ void __launch_bounds__(256) k_fuse2(const float* __restrict__ b1,
                                               const float* __restrict__ W2, int n) {
    __shared__ float W2t[F_H * F_OUT];  // [j][m]
    __shared__ float rs[8][F_H];
    int tid = threadIdx.x;
    for (int t = tid; t < F_H * F_OUT; t += 256) {
        int m = t / F_H, j = t % F_H;
        W2t[j * F_OUT + m] = W2[t];
    }
    __syncthreads();
    int w = tid >> 5, lane = tid & 31;
    int row = blockIdx.x * 8 + w;
    float di = 0.f;
    if (row < n) {
        di = g_dinv[row];
        float2 a  = *(const float2*)(g_acc1 + (size_t)row * F_H + 2 * lane);
        float2 bb = *(const float2*)(b1 + 2 * lane);
        rs[w][2 * lane + 0] = fmaxf(di * a.x + bb.x, 0.f);
        rs[w][2 * lane + 1] = fmaxf(di * a.y + bb.y, 0.f);
    }
    __syncwarp();
    if (row >= n) return;

    float acc = 0.f;
    #pragma unroll
    for (int j = 0; j < F_H; j++) {
        acc += rs[w][j] * W2t[j * F_OUT + lane];
    }
    float o = acc * di;
    g_g2  [(size_t)row * F_OUT + lane] = o;
    g_acc2[(size_t)row * F_OUT + lane] = o;
}

// ---------------- scatter layer 2: acc2[dst] += g2[src], 8 threads/edge ----------------
__global__ void __launch_bounds__(256) k_scatter2(const void* __restrict__ idxp, int E) {
    long long g = (long long)blockIdx.x * blockDim.x + threadIdx.x;
    if (g >= (long long)E * 8) return;
    int e = (int)(g >> 3);
    int c = (int)(g & 7);
    int src, dst;
    if (g_is64) {
        const long long* I = (const long long*)idxp;
        src = (int)I[e]; dst = (int)I[E + e];
    } else {
        const int* I = (const int*)idxp;
        src = I[e]; dst = I[E + e];
    }
    float4 v = ((const float4*)g_g2)[(size_t)src * 8 + c];
    float* a = (float*)(((float4*)g_acc2) + (size_t)dst * 8 + c);
    asm volatile("red.global.add.v4.f32 [%0], {%1,%2,%3,%4};"
                 :: "l"(a), "f"(v.x), "f"(v.y), "f"(v.z), "f"(v.w) : "memory");
}

// ---------------- finalize layer 2 -> output ----------------
__global__ void k_out(const float* __restrict__ b2, float* __restrict__ out, int n) {
    int t = blockIdx.x * blockDim.x + threadIdx.x;
    if (t >= n * F_OUT) return;
    int row = t >> 5;     // F_OUT == 32
    int j   = t & 31;
    out[t] = g_dinv[row] * g_acc2[t] + b2[j];
}

// ---------------- launch ----------------
extern "C" void kernel_launch(void* const* d_in, const int* in_sizes, int n_in,
                              void* d_out, int out_size) {
    const float* x  = (const float*)d_in[0];
    const void*  ei = d_in[1];
    const float* W1 = (const float*)d_in[2];
    const float* b1 = (const float*)d_in[3];
    const float* W2 = (const float*)d_in[4];
    const float* b2 = (const float*)d_in[5];
    float* out = (float*)d_out;

    int N = in_sizes[0] / F_IN;       // 100000
    int E = in_sizes[1] / 2;          // 1600000 (element count same for i32/i64)
    if (N > NN) N = NN;
    if (E > EE) E = EE;

    k_detect<<<1, 32>>>((const unsigned long long*)ei);
    k_init_deg<<<(N + 255) / 256, 256>>>(N);
    k_deg<<<(E + 255) / 256, 256>>>(ei, E);
    k_dinv<<<(N + 255) / 256, 256>>>(N);

    int rowBlocks = (N + 7) / 8;
    k_gemm1<<<rowBlocks, 256>>>(x, W1, N);

    long long t1 = (long long)E * 16;
    k_scatter1<<<(unsigned)((t1 + 255) / 256), 256>>>(ei, E);

    k_fuse2<<<rowBlocks, 256>>>(b1, W2, N);

    long long t2 = (long long)E * 8;
    k_scatter2<<<(unsigned)((t2 + 255) / 256), 256>>>(ei, E);

    k_out<<<(N * F_OUT + 255) / 256, 256>>>(b2, out, N);
}

// round 3
// speedup vs baseline: 1.0662x; 1.0662x over previous
#include <cuda_runtime.h>
#include <stdint.h>

#define NN 100000
#define EE 1600000
#define F_IN 128
#define F_H 64
#define F_OUT 32

// ---------------- device scratch (static allocation only) ----------------
__device__ int   g_is64;
__device__ int   g_cnt[NN];        // in-degree (edges only, excl self-loop)
__device__ int   g_off[NN];        // CSR offsets (exclusive scan of cnt)
__device__ int   g_cur[NN];        // fill cursors
__device__ int   g_bsum[512];      // block sums for scan
__device__ int   g_boff[512];      // block offsets
__device__ int   g_srcs[EE];       // dst-grouped source ids (int32)
__device__ float g_dinv[NN];
__device__ float g_g1[NN * F_H];
__device__ float g_acc1[NN * F_H];
__device__ float g_g2[NN * F_OUT];

// ---------------- dtype detection for edge_index ----------------
__global__ void k_detect(const unsigned long long* __restrict__ idx) {
    if (threadIdx.x == 0) {
        int is64 = 1;
        for (int i = 0; i < 64; i++) {
            if (idx[i] >= (unsigned long long)NN) { is64 = 0; break; }
        }
        g_is64 = is64;
    }
}

__global__ void k_zero(int n) {
    int i = blockIdx.x * blockDim.x + threadIdx.x;
    if (i < n) g_cnt[i] = 0;
}

__global__ void k_count(const void* __restrict__ idxp, int E) {
    int e = blockIdx.x * blockDim.x + threadIdx.x;
    if (e >= E) return;
    int dst;
    if (g_is64) dst = (int)((const long long*)idxp)[E + e];
    else        dst = ((const int*)idxp)[E + e];
    atomicAdd(&g_cnt[dst], 1);
}

// ---------------- 3-kernel exclusive scan over g_cnt -> g_off ----------------
__global__ void k_scan1(int n) {
    __shared__ int sh[256];
    int t = threadIdx.x;
    int idx = blockIdx.x * 256 + t;
    int c = (idx < n) ? g_cnt[idx] : 0;
    sh[t] = c;
    __syncthreads();
    #pragma unroll
    for (int o = 1; o < 256; o <<= 1) {
        int x = sh[t];
        int y = (t >= o) ? sh[t - o] : 0;
        __syncthreads();
        sh[t] = x + y;
        __syncthreads();
    }
    int incl = sh[t];
    if (idx < n) g_off[idx] = incl - c;
    if (t == 255) g_bsum[blockIdx.x] = incl;
}

__global__ void k_scan2(int nb) {
    __shared__ int sh[512];
    int t = threadIdx.x;
    int v = (t < nb) ? g_bsum[t] : 0;
    sh[t] = v;
    __syncthreads();
    #pragma unroll
    for (int o = 1; o < 512; o <<= 1) {
        int x = sh[t];
        int y = (t >= o) ? sh[t - o] : 0;
        __syncthreads();
        sh[t] = x + y;
        __syncthreads();
    }
    if (t < nb) g_boff[t] = sh[t] - v;
}

__global__ void k_scan3(int n) {
    int i = blockIdx.x * blockDim.x + threadIdx.x;
    if (i >= n) return;
    int off = g_off[i] + g_boff[i >> 8];
    g_off[i] = off;
    g_cur[i] = off;
    g_dinv[i] = rsqrtf((float)(g_cnt[i] + 1));   // +1 self-loop
}

__global__ void k_fill(const void* __restrict__ idxp, int E) {
    int e = blockIdx.x * blockDim.x + threadIdx.x;
    if (e >= E) return;
    int src, dst;
    if (g_is64) {
        const long long* I = (const long long*)idxp;
        src = (int)I[e]; dst = (int)I[E + e];
    } else {
        const int* I = (const int*)idxp;
        src = I[e]; dst = I[E + e];
    }
    int pos = atomicAdd(&g_cur[dst], 1);
    g_srcs[pos] = src;
}

// ---------------- GEMM1: g1[i][j] = dinv[i] * dot(x[i,:], W1[j,:]) ----------------
__global__ void __launch_bounds__(256) k_gemm1(const float* __restrict__ x,
                                               const float* __restrict__ W1, int n) {
    __shared__ float W1t[F_IN * F_H];   // [k][j]
    __shared__ float xs[8][F_IN];
    int tid = threadIdx.x;
    for (int t = tid; t < F_IN * F_H; t += 256) {
        int j = t / F_IN, k = t % F_IN;
        W1t[k * F_H + j] = W1[t];
    }
    __syncthreads();
    int w = tid >> 5, lane = tid & 31;
    int row = blockIdx.x * 8 + w;
    if (row < n) {
        ((float4*)xs[w])[lane] = ((const float4*)(x + (size_t)row * F_IN))[lane];
    }
    __syncwarp();
    if (row >= n) return;

    float a0 = 0.f, a1 = 0.f;
    const float* xr = xs[w];
    #pragma unroll
    for (int k = 0; k < F_IN; k += 4) {
        float4 xk = *(const float4*)(xr + k);
        float2 w0 = *(const float2*)(W1t + (k + 0) * F_H + 2 * lane);
        float2 w1 = *(const float2*)(W1t + (k + 1) * F_H + 2 * lane);
        float2 w2 = *(const float2*)(W1t + (k + 2) * F_H + 2 * lane);
        float2 w3 = *(const float2*)(W1t + (k + 3) * F_H + 2 * lane);
        a0 += xk.x * w0.x + xk.y * w1.x + xk.z * w2.x + xk.w * w3.x;
        a1 += xk.x * w0.y + xk.y * w1.y + xk.z * w2.y + xk.w * w3.y;
    }
    float di = g_dinv[row];
    *(float2*)(g_g1 + (size_t)row * F_H + 2 * lane) = make_float2(a0 * di, a1 * di);
}

// ---------------- gather-reduce layer 1: warp per dst node ----------------
__global__ void __launch_bounds__(256) k_agg1(int n) {
    int tid = threadIdx.x;
    int w = tid >> 5, lane = tid & 31;
    int i = blockIdx.x * 8 + w;
    if (i >= n) return;
    int start = g_off[i];
    int len = g_cnt[i];
    float2 acc = *(const float2*)(g_g1 + (size_t)i * F_H + 2 * lane);  // self-loop
    for (int base = 0; base < len; base += 32) {
        int m = min(32, len - base);
        int s = (lane < m) ? __ldg(&g_srcs[start + base + lane]) : 0;
        int k = 0;
        for (; k + 4 <= m; k += 4) {
            int s0 = __shfl_sync(0xffffffffu, s, k + 0);
            int s1 = __shfl_sync(0xffffffffu, s, k + 1);
            int s2 = __shfl_sync(0xffffffffu, s, k + 2);
            int s3 = __shfl_sync(0xffffffffu, s, k + 3);
            float2 v0 = *(const float2*)(g_g1 + (size_t)s0 * F_H + 2 * lane);
            float2 v1 = *(const float2*)(g_g1 + (size_t)s1 * F_H + 2 * lane);
            float2 v2 = *(const float2*)(g_g1 + (size_t)s2 * F_H + 2 * lane);
            float2 v3 = *(const float2*)(g_g1 + (size_t)s3 * F_H + 2 * lane);
            acc.x += v0.x + v1.x + v2.x + v3.x;
            acc.y += v0.y + v1.y + v2.y + v3.y;
        }
        for (; k < m; k++) {
            int sk = __shfl_sync(0xffffffffu, s, k);
            float2 v = *(const float2*)(g_g1 + (size_t)sk * F_H + 2 * lane);
            acc.x += v.x; acc.y += v.y;
        }
    }
    *(float2*)(g_acc1 + (size_t)i * F_H + 2 * lane) = acc;
}

// ---------------- fused: finalize1 + ReLU + GEMM2 ----------------
__global__ void __launch_bounds__(256) k_fuse2(const float* __restrict__ b1,
                                               const float* __restrict__ W2, int n) {
    __shared__ float W2t[F_H * F_OUT];  // [j][m]
    __shared__ float rs[8][F_H];
    int tid = threadIdx.x;
    for (int t = tid; t < F_H * F_OUT; t += 256) {
        int m = t / F_H, j = t % F_H;
        W2t[j * F_OUT + m] = W2[t];
    }
    __syncthreads();
    int w = tid >> 5, lane = tid & 31;
    int row = blockIdx.x * 8 + w;
    float di = 0.f;
    if (row < n) {
        di = g_dinv[row];
        float2 a  = *(const float2*)(g_acc1 + (size_t)row * F_H + 2 * lane);
        float2 bb = *(const float2*)(b1 + 2 * lane);
        rs[w][2 * lane + 0] = fmaxf(di * a.x + bb.x, 0.f);
        rs[w][2 * lane + 1] = fmaxf(di * a.y + bb.y, 0.f);
    }
    __syncwarp();
    if (row >= n) return;

    float acc = 0.f;
    #pragma unroll
    for (int j = 0; j < F_H; j++) {
        acc += rs[w][j] * W2t[j * F_OUT + lane];
    }
    g_g2[(size_t)row * F_OUT + lane] = acc * di;
}

// ---------------- gather-reduce layer 2 + epilogue -> out ----------------
__global__ void __launch_bounds__(256) k_agg2(const float* __restrict__ b2,
                                              float* __restrict__ out, int n) {
    int tid = threadIdx.x;
    int w = tid >> 5, lane = tid & 31;
    int i = blockIdx.x * 8 + w;
    if (i >= n) return;
    int start = g_off[i];
    int len = g_cnt[i];
    float acc = g_g2[(size_t)i * F_OUT + lane];   // self-loop
    for (int base = 0; base < len; base += 32) {
        int m = min(32, len - base);
        int s = (lane < m) ? __ldg(&g_srcs[start + base + lane]) : 0;
        int k = 0;
        for (; k + 4 <= m; k += 4) {
            int s0 = __shfl_sync(0xffffffffu, s, k + 0);
            int s1 = __shfl_sync(0xffffffffu, s, k + 1);
            int s2 = __shfl_sync(0xffffffffu, s, k + 2);
            int s3 = __shfl_sync(0xffffffffu, s, k + 3);
            float v0 = g_g2[(size_t)s0 * F_OUT + lane];
            float v1 = g_g2[(size_t)s1 * F_OUT + lane];
            float v2 = g_g2[(size_t)s2 * F_OUT + lane];
            float v3 = g_g2[(size_t)s3 * F_OUT + lane];
            acc += v0 + v1 + v2 + v3;
        }
        for (; k < m; k++) {
            int sk = __shfl_sync(0xffffffffu, s, k);
            acc += g_g2[(size_t)sk * F_OUT + lane];
        }
    }
    out[(size_t)i * F_OUT + lane] = g_dinv[i] * acc + b2[lane];
}

// ---------------- launch ----------------
extern "C" void kernel_launch(void* const* d_in, const int* in_sizes, int n_in,
                              void* d_out, int out_size) {
    const float* x  = (const float*)d_in[0];
    const void*  ei = d_in[1];
    const float* W1 = (const float*)d_in[2];
    const float* b1 = (const float*)d_in[3];
    const float* W2 = (const float*)d_in[4];
    const float* b2 = (const float*)d_in[5];
    float* out = (float*)d_out;

    int N = in_sizes[0] / F_IN;       // 100000
    int E = in_sizes[1] / 2;          // 1600000
    if (N > NN) N = NN;
    if (E > EE) E = EE;

    int nB = (N + 255) / 256;         // 391 blocks for node-sized work
    int eB = (E + 255) / 256;
    int rowBlocks = (N + 7) / 8;

    k_detect<<<1, 32>>>((const unsigned long long*)ei);
    k_zero<<<nB, 256>>>(N);
    k_count<<<eB, 256>>>(ei, E);
    k_scan1<<<nB, 256>>>(N);
    k_scan2<<<1, 512>>>(nB);
    k_scan3<<<nB, 256>>>(N);
    k_fill<<<eB, 256>>>(ei, E);

    k_gemm1<<<rowBlocks, 256>>>(x, W1, N);
    k_agg1<<<rowBlocks, 256>>>(N);
    k_fuse2<<<rowBlocks, 256>>>(b1, W2, N);
    k_agg2<<<rowBlocks, 256>>>(b2, out, N);
}

// round 4
// speedup vs baseline: 1.0668x; 1.0006x over previous
#include <cuda_runtime.h>
#include <stdint.h>

#define NN 100000
#define EE 1600000
#define F_IN 128
#define F_H 64
#define F_OUT 32

// ---------------- device scratch (static allocation only) ----------------
__device__ int   g_is64;
__device__ int   g_cnt[NN];        // in-degree (edges only, excl self-loop)
__device__ int   g_off[NN];        // CSR offsets (exclusive scan of cnt)
__device__ int   g_cur[NN];        // fill cursors
__device__ int   g_bsum[512];      // block sums for scan
__device__ int   g_boff[512];      // block offsets
__device__ int   g_srcs[EE];       // dst-grouped source ids (int32)
__device__ float g_dinv[NN];
__device__ float g_g1[NN * F_H];
__device__ float g_acc1[NN * F_H];
__device__ float g_g2[NN * F_OUT];

// ---------------- dtype detection for edge_index ----------------
__global__ void k_detect(const unsigned long long* __restrict__ idx) {
    if (threadIdx.x == 0) {
        int is64 = 1;
        for (int i = 0; i < 64; i++) {
            if (idx[i] >= (unsigned long long)NN) { is64 = 0; break; }
        }
        g_is64 = is64;
    }
}

__global__ void k_zero(int n) {
    int i = blockIdx.x * blockDim.x + threadIdx.x;
    if (i < n) g_cnt[i] = 0;
}

__global__ void k_count(const void* __restrict__ idxp, int E) {
    int e = blockIdx.x * blockDim.x + threadIdx.x;
    if (e >= E) return;
    int dst;
    if (g_is64) dst = (int)((const long long*)idxp)[E + e];
    else        dst = ((const int*)idxp)[E + e];
    atomicAdd(&g_cnt[dst], 1);
}

// ---------------- 3-kernel exclusive scan over g_cnt -> g_off ----------------
__global__ void k_scan1(int n) {
    __shared__ int sh[256];
    int t = threadIdx.x;
    int idx = blockIdx.x * 256 + t;
    int c = (idx < n) ? g_cnt[idx] : 0;
    sh[t] = c;
    __syncthreads();
    #pragma unroll
    for (int o = 1; o < 256; o <<= 1) {
        int x = sh[t];
        int y = (t >= o) ? sh[t - o] : 0;
        __syncthreads();
        sh[t] = x + y;
        __syncthreads();
    }
    int incl = sh[t];
    if (idx < n) g_off[idx] = incl - c;
    if (t == 255) g_bsum[blockIdx.x] = incl;
}

__global__ void k_scan2(int nb) {
    __shared__ int sh[512];
    int t = threadIdx.x;
    int v = (t < nb) ? g_bsum[t] : 0;
    sh[t] = v;
    __syncthreads();
    #pragma unroll
    for (int o = 1; o < 512; o <<= 1) {
        int x = sh[t];
        int y = (t >= o) ? sh[t - o] : 0;
        __syncthreads();
        sh[t] = x + y;
        __syncthreads();
    }
    if (t < nb) g_boff[t] = sh[t] - v;
}

__global__ void k_scan3(int n) {
    int i = blockIdx.x * blockDim.x + threadIdx.x;
    if (i >= n) return;
    int off = g_off[i] + g_boff[i >> 8];
    g_off[i] = off;
    g_cur[i] = off;
    g_dinv[i] = rsqrtf((float)(g_cnt[i] + 1));   // +1 self-loop
}

__global__ void k_fill(const void* __restrict__ idxp, int E) {
    int e = blockIdx.x * blockDim.x + threadIdx.x;
    if (e >= E) return;
    int src, dst;
    if (g_is64) {
        const long long* I = (const long long*)idxp;
        src = (int)I[e]; dst = (int)I[E + e];
    } else {
        const int* I = (const int*)idxp;
        src = I[e]; dst = I[E + e];
    }
    int pos = atomicAdd(&g_cur[dst], 1);
    g_srcs[pos] = src;
}

// ---------------- GEMM1: g1[i][j] = dinv[i] * dot(x[i,:], W1[j,:]) ----------------
__global__ void __launch_bounds__(256) k_gemm1(const float* __restrict__ x,
                                               const float* __restrict__ W1, int n) {
    __shared__ float W1t[F_IN * F_H];   // [k][j]
    __shared__ float xs[8][F_IN];
    int tid = threadIdx.x;
    for (int t = tid; t < F_IN * F_H; t += 256) {
        int j = t / F_IN, k = t % F_IN;
        W1t[k * F_H + j] = W1[t];
    }
    __syncthreads();
    int w = tid >> 5, lane = tid & 31;
    int row = blockIdx.x * 8 + w;
    if (row < n) {
        ((float4*)xs[w])[lane] = ((const float4*)(x + (size_t)row * F_IN))[lane];
    }
    __syncwarp();
    if (row >= n) return;

    float a0 = 0.f, a1 = 0.f;
    const float* xr = xs[w];
    #pragma unroll
    for (int k = 0; k < F_IN; k += 4) {
        float4 xk = *(const float4*)(xr + k);
        float2 w0 = *(const float2*)(W1t + (k + 0) * F_H + 2 * lane);
        float2 w1 = *(const float2*)(W1t + (k + 1) * F_H + 2 * lane);
        float2 w2 = *(const float2*)(W1t + (k + 2) * F_H + 2 * lane);
        float2 w3 = *(const float2*)(W1t + (k + 3) * F_H + 2 * lane);
        a0 += xk.x * w0.x + xk.y * w1.x + xk.z * w2.x + xk.w * w3.x;
        a1 += xk.x * w0.y + xk.y * w1.y + xk.z * w2.y + xk.w * w3.y;
    }
    float di = g_dinv[row];
    *(float2*)(g_g1 + (size_t)row * F_H + 2 * lane) = make_float2(a0 * di, a1 * di);
}

// ---------------- gather-reduce layer 1: warp per dst node ----------------
__global__ void __launch_bounds__(256) k_agg1(int n) {
    int tid = threadIdx.x;
    int w = tid >> 5, lane = tid & 31;
    int i = blockIdx.x * 8 + w;
    if (i >= n) return;
    int start = g_off[i];
    int len = g_cnt[i];
    float2 acc = *(const float2*)(g_g1 + (size_t)i * F_H + 2 * lane);  // self-loop
    for (int base = 0; base < len; base += 32) {
        int m = min(32, len - base);
        int s = (lane < m) ? __ldg(&g_srcs[start + base + lane]) : 0;
        int k = 0;
        for (; k + 4 <= m; k += 4) {
            int s0 = __shfl_sync(0xffffffffu, s, k + 0);
            int s1 = __shfl_sync(0xffffffffu, s, k + 1);
            int s2 = __shfl_sync(0xffffffffu, s, k + 2);
            int s3 = __shfl_sync(0xffffffffu, s, k + 3);
            float2 v0 = *(const float2*)(g_g1 + (size_t)s0 * F_H + 2 * lane);
            float2 v1 = *(const float2*)(g_g1 + (size_t)s1 * F_H + 2 * lane);
            float2 v2 = *(const float2*)(g_g1 + (size_t)s2 * F_H + 2 * lane);
            float2 v3 = *(const float2*)(g_g1 + (size_t)s3 * F_H + 2 * lane);
            acc.x += v0.x + v1.x + v2.x + v3.x;
            acc.y += v0.y + v1.y + v2.y + v3.y;
        }
        for (; k < m; k++) {
            int sk = __shfl_sync(0xffffffffu, s, k);
            float2 v = *(const float2*)(g_g1 + (size_t)sk * F_H + 2 * lane);
            acc.x += v.x; acc.y += v.y;
        }
    }
    *(float2*)(g_acc1 + (size_t)i * F_H + 2 * lane) = acc;
}

// ---------------- fused: finalize1 + ReLU + GEMM2 ----------------
__global__ void __launch_bounds__(256) k_fuse2(const float* __restrict__ b1,
                                               const float* __restrict__ W2, int n) {
    __shared__ float W2t[F_H * F_OUT];  // [j][m]
    __shared__ float rs[8][F_H];
    int tid = threadIdx.x;
    for (int t = tid; t < F_H * F_OUT; t += 256) {
        int m = t / F_H, j = t % F_H;
        W2t[j * F_OUT + m] = W2[t];
    }
    __syncthreads();
    int w = tid >> 5, lane = tid & 31;
    int row = blockIdx.x * 8 + w;
    float di = 0.f;
    if (row < n) {
        di = g_dinv[row];
        float2 a  = *(const float2*)(g_acc1 + (size_t)row * F_H + 2 * lane);
        float2 bb = *(const float2*)(b1 + 2 * lane);
        rs[w][2 * lane + 0] = fmaxf(di * a.x + bb.x, 0.f);
        rs[w][2 * lane + 1] = fmaxf(di * a.y + bb.y, 0.f);
    }
    __syncwarp();
    if (row >= n) return;

    float acc = 0.f;
    #pragma unroll
    for (int j = 0; j < F_H; j++) {
        acc += rs[w][j] * W2t[j * F_OUT + lane];
    }
    g_g2[(size_t)row * F_OUT + lane] = acc * di;
}

// ---------------- gather-reduce layer 2 + epilogue -> out ----------------
__global__ void __launch_bounds__(256) k_agg2(const float* __restrict__ b2,
                                              float* __restrict__ out, int n) {
    int tid = threadIdx.x;
    int w = tid >> 5, lane = tid & 31;
    int i = blockIdx.x * 8 + w;
    if (i >= n) return;
    int start = g_off[i];
    int len = g_cnt[i];
    float acc = g_g2[(size_t)i * F_OUT + lane];   // self-loop
    for (int base = 0; base < len; base += 32) {
        int m = min(32, len - base);
        int s = (lane < m) ? __ldg(&g_srcs[start + base + lane]) : 0;
        int k = 0;
        for (; k + 4 <= m; k += 4) {
            int s0 = __shfl_sync(0xffffffffu, s, k + 0);
            int s1 = __shfl_sync(0xffffffffu, s, k + 1);
            int s2 = __shfl_sync(0xffffffffu, s, k + 2);
            int s3 = __shfl_sync(0xffffffffu, s, k + 3);
            float v0 = g_g2[(size_t)s0 * F_OUT + lane];
            float v1 = g_g2[(size_t)s1 * F_OUT + lane];
            float v2 = g_g2[(size_t)s2 * F_OUT + lane];
            float v3 = g_g2[(size_t)s3 * F_OUT + lane];
            acc += v0 + v1 + v2 + v3;
        }
        for (; k < m; k++) {
            int sk = __shfl_sync(0xffffffffu, s, k);
            acc += g_g2[(size_t)sk * F_OUT + lane];
        }
    }
    out[(size_t)i * F_OUT + lane] = g_dinv[i] * acc + b2[lane];
}

// ---------------- launch ----------------
extern "C" void kernel_launch(void* const* d_in, const int* in_sizes, int n_in,
                              void* d_out, int out_size) {
    const float* x  = (const float*)d_in[0];
    const void*  ei = d_in[1];
    const float* W1 = (const float*)d_in[2];
    const float* b1 = (const float*)d_in[3];
    const float* W2 = (const float*)d_in[4];
    const float* b2 = (const float*)d_in[5];
    float* out = (float*)d_out;

    int N = in_sizes[0] / F_IN;       // 100000
    int E = in_sizes[1] / 2;          // 1600000
    if (N > NN) N = NN;
    if (E > EE) E = EE;

    int nB = (N + 255) / 256;         // 391 blocks for node-sized work
    int eB = (E + 255) / 256;
    int rowBlocks = (N + 7) / 8;

    k_detect<<<1, 32>>>((const unsigned long long*)ei);
    k_zero<<<nB, 256>>>(N);
    k_count<<<eB, 256>>>(ei, E);
    k_scan1<<<nB, 256>>>(N);
    k_scan2<<<1, 512>>>(nB);
    k_scan3<<<nB, 256>>>(N);
    k_fill<<<eB, 256>>>(ei, E);

    k_gemm1<<<rowBlocks, 256>>>(x, W1, N);
    k_agg1<<<rowBlocks, 256>>>(N);
    k_fuse2<<<rowBlocks, 256>>>(b1, W2, N);
    k_agg2<<<rowBlocks, 256>>>(b2, out, N);
}

// round 5
// speedup vs baseline: 2.5275x; 2.3694x over previous
#include <cuda_runtime.h>
#include <stdint.h>

#define NN 100000
#define EE 1600000
#define F_IN 128
#define F_H 64
#define F_OUT 32

// ---------------- device scratch (static allocation only) ----------------
__device__ int   g_is64;
__device__ int   g_cnt[NN];        // in-degree (edges only, excl self-loop)
__device__ int   g_off[NN];        // CSR offsets (exclusive scan of cnt)
__device__ int   g_cur[NN];        // fill cursors
__device__ int   g_bsum[512];      // block sums for scan
__device__ int   g_boff[512];      // block offsets
__device__ int   g_srcs[EE];       // dst-grouped source ids (int32)
__device__ float g_dinv[NN];
__device__ float g_g1[NN * F_H];
__device__ float g_acc1[NN * F_H];
__device__ float g_g2[NN * F_OUT];

// ---------------- fused: zero cnt + dtype detection ----------------
__global__ void k_detzero(const unsigned long long* __restrict__ idx, int n) {
    int i = blockIdx.x * blockDim.x + threadIdx.x;
    if (i < n) g_cnt[i] = 0;
    if (blockIdx.x == 0 && threadIdx.x < 32) {
        // int64 data: every u64 word is a node id < NN.
        // int32 data: u64 packs two random ids; high word nonzero w.p. ~1-1e-5.
        unsigned mask = __ballot_sync(0xffffffffu,
                                      idx[threadIdx.x] >= (unsigned long long)NN);
        if (threadIdx.x == 0) g_is64 = (mask == 0u) ? 1 : 0;
    }
}

__global__ void k_count(const void* __restrict__ idxp, int E) {
    int e = blockIdx.x * blockDim.x + threadIdx.x;
    if (e >= E) return;
    int dst;
    if (g_is64) dst = (int)((const long long*)idxp)[E + e];
    else        dst = ((const int*)idxp)[E + e];
    atomicAdd(&g_cnt[dst], 1);
}

// ---------------- 3-kernel exclusive scan over g_cnt -> g_off ----------------
__global__ void k_scan1(int n) {
    __shared__ int sh[256];
    int t = threadIdx.x;
    int idx = blockIdx.x * 256 + t;
    int c = (idx < n) ? g_cnt[idx] : 0;
    sh[t] = c;
    __syncthreads();
    #pragma unroll
    for (int o = 1; o < 256; o <<= 1) {
        int x = sh[t];
        int y = (t >= o) ? sh[t - o] : 0;
        __syncthreads();
        sh[t] = x + y;
        __syncthreads();
    }
    int incl = sh[t];
    if (idx < n) g_off[idx] = incl - c;
    if (t == 255) g_bsum[blockIdx.x] = incl;
}

__global__ void k_scan2(int nb) {
    __shared__ int sh[512];
    int t = threadIdx.x;
    int v = (t < nb) ? g_bsum[t] : 0;
    sh[t] = v;
    __syncthreads();
    #pragma unroll
    for (int o = 1; o < 512; o <<= 1) {
        int x = sh[t];
        int y = (t >= o) ? sh[t - o] : 0;
        __syncthreads();
        sh[t] = x + y;
        __syncthreads();
    }
    if (t < nb) g_boff[t] = sh[t] - v;
}

__global__ void k_scan3(int n) {
    int i = blockIdx.x * blockDim.x + threadIdx.x;
    if (i >= n) return;
    int off = g_off[i] + g_boff[i >> 8];
    g_off[i] = off;
    g_cur[i] = off;
    g_dinv[i] = rsqrtf((float)(g_cnt[i] + 1));   // +1 self-loop
}

__global__ void k_fill(const void* __restrict__ idxp, int E) {
    int e = blockIdx.x * blockDim.x + threadIdx.x;
    if (e >= E) return;
    int src, dst;
    if (g_is64) {
        const long long* I = (const long long*)idxp;
        src = (int)I[e]; dst = (int)I[E + e];
    } else {
        const int* I = (const int*)idxp;
        src = I[e]; dst = I[E + e];
    }
    int pos = atomicAdd(&g_cur[dst], 1);
    g_srcs[pos] = src;
}

// ---------------- GEMM1: g1[i][j] = dinv[i] * dot(x[i,:], W1[j,:]) ----------------
// 32 rows/block, 8 warps x 4 rows each, register-blocked accumulators.
__global__ void __launch_bounds__(256) k_gemm1(const float* __restrict__ x,
                                               const float* __restrict__ W1, int n) {
    __shared__ float W1t[F_IN * F_H];   // [k][j]  32KB
    __shared__ float xs[32][F_IN];      // 16KB
    int tid = threadIdx.x;
    for (int t = tid; t < F_IN * F_H; t += 256) {
        int j = t / F_IN, k = t % F_IN;
        W1t[k * F_H + j] = W1[t];
    }
    int blockRow = blockIdx.x * 32;
    for (int t = tid; t < 32 * 32; t += 256) {      // 1024 float4 loads
        int r = t >> 5, s = t & 31;
        if (blockRow + r < n)
            ((float4*)xs[r])[s] = ((const float4*)(x + (size_t)(blockRow + r) * F_IN))[s];
    }
    __syncthreads();

    int w = tid >> 5, lane = tid & 31;
    int r0 = w * 4;
    float acc[4][2];
    #pragma unroll
    for (int r = 0; r < 4; r++) { acc[r][0] = 0.f; acc[r][1] = 0.f; }

    #pragma unroll 4
    for (int k = 0; k < F_IN; k += 4) {
        float2 w0 = *(const float2*)(W1t + (k + 0) * F_H + 2 * lane);
        float2 w1 = *(const float2*)(W1t + (k + 1) * F_H + 2 * lane);
        float2 w2 = *(const float2*)(W1t + (k + 2) * F_H + 2 * lane);
        float2 w3 = *(const float2*)(W1t + (k + 3) * F_H + 2 * lane);
        #pragma unroll
        for (int r = 0; r < 4; r++) {
            float4 xk = *(const float4*)(xs[r0 + r] + k);
            acc[r][0] += xk.x * w0.x + xk.y * w1.x + xk.z * w2.x + xk.w * w3.x;
            acc[r][1] += xk.x * w0.y + xk.y * w1.y + xk.z * w2.y + xk.w * w3.y;
        }
    }
    #pragma unroll
    for (int r = 0; r < 4; r++) {
        int row = blockRow + r0 + r;
        if (row < n) {
            float di = rsqrtf((float)(g_cnt[row] + 1));
            *(float2*)(g_g1 + (size_t)row * F_H + 2 * lane) =
                make_float2(acc[r][0] * di, acc[r][1] * di);
        }
    }
}

// ---------------- gather-reduce layer 1: warp per dst node, unroll 8 ----------------
__global__ void __launch_bounds__(256) k_agg1(int n) {
    int tid = threadIdx.x;
    int w = tid >> 5, lane = tid & 31;
    int i = blockIdx.x * 8 + w;
    if (i >= n) return;
    int start = g_off[i];
    int len = g_cnt[i];
    float2 acc = *(const float2*)(g_g1 + (size_t)i * F_H + 2 * lane);  // self-loop
    for (int base = 0; base < len; base += 32) {
        int m = min(32, len - base);
        int s = (lane < m) ? __ldg(&g_srcs[start + base + lane]) : 0;
        int k = 0;
        for (; k + 8 <= m; k += 8) {
            int ss[8];
            #pragma unroll
            for (int u = 0; u < 8; u++) ss[u] = __shfl_sync(0xffffffffu, s, k + u);
            float2 v[8];
            #pragma unroll
            for (int u = 0; u < 8; u++)
                v[u] = *(const float2*)(g_g1 + (size_t)ss[u] * F_H + 2 * lane);
            #pragma unroll
            for (int u = 0; u < 8; u++) { acc.x += v[u].x; acc.y += v[u].y; }
        }
        for (; k < m; k++) {
            int sk = __shfl_sync(0xffffffffu, s, k);
            float2 v = *(const float2*)(g_g1 + (size_t)sk * F_H + 2 * lane);
            acc.x += v.x; acc.y += v.y;
        }
    }
    *(float2*)(g_acc1 + (size_t)i * F_H + 2 * lane) = acc;
}

// ---------------- fused: finalize1 + ReLU + GEMM2 (4 rows/warp) ----------------
__global__ void __launch_bounds__(256) k_fuse2(const float* __restrict__ b1,
                                               const float* __restrict__ W2, int n) {
    __shared__ float W2t[F_H * F_OUT];  // [j][m]  8KB
    __shared__ float rs[32][F_H];       // 8KB
    int tid = threadIdx.x;
    for (int t = tid; t < F_H * F_OUT; t += 256) {
        int m = t / F_H, j = t % F_H;
        W2t[j * F_OUT + m] = W2[t];
    }
    int blockRow = blockIdx.x * 32;
    for (int t = tid; t < 32 * F_H; t += 256) {
        int r = t >> 6, j = t & 63;
        int row = blockRow + r;
        if (row < n) {
            float di = g_dinv[row];
            rs[r][j] = fmaxf(di * g_acc1[(size_t)row * F_H + j] + b1[j], 0.f);
        }
    }
    __syncthreads();

    int w = tid >> 5, lane = tid & 31;
    int r0 = w * 4;
    float acc[4] = {0.f, 0.f, 0.f, 0.f};
    #pragma unroll 8
    for (int j = 0; j < F_H; j++) {
        float wv = W2t[j * F_OUT + lane];
        #pragma unroll
        for (int r = 0; r < 4; r++) acc[r] += rs[r0 + r][j] * wv;
    }
    #pragma unroll
    for (int r = 0; r < 4; r++) {
        int row = blockRow + r0 + r;
        if (row < n)
            g_g2[(size_t)row * F_OUT + lane] = acc[r] * g_dinv[row];
    }
}

// ---------------- gather-reduce layer 2 + epilogue -> out, unroll 8 ----------------
__global__ void __launch_bounds__(256) k_agg2(const float* __restrict__ b2,
                                              float* __restrict__ out, int n) {
    int tid = threadIdx.x;
    int w = tid >> 5, lane = tid & 31;
    int i = blockIdx.x * 8 + w;
    if (i >= n) return;
    int start = g_off[i];
    int len = g_cnt[i];
    float acc = g_g2[(size_t)i * F_OUT + lane];   // self-loop
    for (int base = 0; base < len; base += 32) {
        int m = min(32, len - base);
        int s = (lane < m) ? __ldg(&g_srcs[start + base + lane]) : 0;
        int k = 0;
        for (; k + 8 <= m; k += 8) {
            int ss[8];
            #pragma unroll
            for (int u = 0; u < 8; u++) ss[u] = __shfl_sync(0xffffffffu, s, k + u);
            float v[8];
            #pragma unroll
            for (int u = 0; u < 8; u++) v[u] = g_g2[(size_t)ss[u] * F_OUT + lane];
            #pragma unroll
            for (int u = 0; u < 8; u++) acc += v[u];
        }
        for (; k < m; k++) {
            int sk = __shfl_sync(0xffffffffu, s, k);
            acc += g_g2[(size_t)sk * F_OUT + lane];
        }
    }
    out[(size_t)i * F_OUT + lane] = g_dinv[i] * acc + b2[lane];
}

// ---------------- launch ----------------
extern "C" void kernel_launch(void* const* d_in, const int* in_sizes, int n_in,
                              void* d_out, int out_size) {
    const float* x  = (const float*)d_in[0];
    const void*  ei = d_in[1];
    const float* W1 = (const float*)d_in[2];
    const float* b1 = (const float*)d_in[3];
    const float* W2 = (const float*)d_in[4];
    const float* b2 = (const float*)d_in[5];
    float* out = (float*)d_out;

    int N = in_sizes[0] / F_IN;       // 100000
    int E = in_sizes[1] / 2;          // 1600000
    if (N > NN) N = NN;
    if (E > EE) E = EE;

    int nB = (N + 255) / 256;         // 391
    int eB = (E + 255) / 256;
    int tileBlocks = (N + 31) / 32;   // 3125
    int aggBlocks  = (N + 7) / 8;     // 12500

    k_detzero<<<nB, 256>>>((const unsigned long long*)ei, N);  // 0
    k_count<<<eB, 256>>>(ei, E);                               // 1
    k_scan1<<<nB, 256>>>(N);                                   // 2
    k_gemm1<<<tileBlocks, 256>>>(x, W1, N);                    // 3  <- profiled slot
    k_scan2<<<1, 512>>>(nB);                                   // 4
    k_scan3<<<nB, 256>>>(N);                                   // 5
    k_fill<<<eB, 256>>>(ei, E);                                // 6
    k_agg1<<<aggBlocks, 256>>>(N);                             // 7
    k_fuse2<<<tileBlocks, 256>>>(b1, W2, N);                   // 8
    k_agg2<<<aggBlocks, 256>>>(b2, out, N);                    // 9
}

// round 6
// speedup vs baseline: 3.2297x; 1.2778x over previous
#include <cuda_runtime.h>
#include <stdint.h>

#define NN 100000
#define EE 1600000
#define F_IN 128
#define F_H 64
#define F_OUT 32

// ---------------- device scratch (static allocation only) ----------------
__device__ int   g_is64;
__device__ int   g_cnt[NN];        // in-degree (edges only, excl self-loop)
__device__ int   g_off[NN];        // CSR offsets (exclusive scan of cnt)
__device__ int   g_cur[NN];        // fill cursors
__device__ int   g_bsum[512];      // block sums for scan
__device__ int   g_boff[512];      // block offsets
__device__ int   g_srcs[EE];       // dst-grouped source ids (int32)
__device__ float g_dinv[NN];
__device__ float g_g1[NN * F_H];
__device__ float g_acc1[NN * F_H];
__device__ float g_g2[NN * F_OUT];

// Blackwell packed f32x2 FMA (2 independent fp32 FMAs per instruction)
__device__ __forceinline__ unsigned long long fma2(unsigned long long a,
                                                   unsigned long long b,
                                                   unsigned long long c) {
    unsigned long long d;
    asm("fma.rn.f32x2 %0, %1, %2, %3;" : "=l"(d) : "l"(a), "l"(b), "l"(c));
    return d;
}
union F2U { float2 f; unsigned long long u; };

// ---------------- fused: zero cnt + dtype detection ----------------
__global__ void k_detzero(const unsigned long long* __restrict__ idx, int n) {
    int i = blockIdx.x * blockDim.x + threadIdx.x;
    if (i < n) g_cnt[i] = 0;
    if (blockIdx.x == 0 && threadIdx.x < 32) {
        unsigned mask = __ballot_sync(0xffffffffu,
                                      idx[threadIdx.x] >= (unsigned long long)NN);
        if (threadIdx.x == 0) g_is64 = (mask == 0u) ? 1 : 0;
    }
}

__global__ void k_count(const void* __restrict__ idxp, int E) {
    int e = blockIdx.x * blockDim.x + threadIdx.x;
    if (e >= E) return;
    int dst;
    if (g_is64) dst = (int)((const long long*)idxp)[E + e];
    else        dst = ((const int*)idxp)[E + e];
    atomicAdd(&g_cnt[dst], 1);
}

// ---------------- 3-kernel exclusive scan over g_cnt -> g_off ----------------
__global__ void k_scan1(int n) {
    __shared__ int sh[256];
    int t = threadIdx.x;
    int idx = blockIdx.x * 256 + t;
    int c = (idx < n) ? g_cnt[idx] : 0;
    sh[t] = c;
    __syncthreads();
    #pragma unroll
    for (int o = 1; o < 256; o <<= 1) {
        int x = sh[t];
        int y = (t >= o) ? sh[t - o] : 0;
        __syncthreads();
        sh[t] = x + y;
        __syncthreads();
    }
    int incl = sh[t];
    if (idx < n) g_off[idx] = incl - c;
    if (t == 255) g_bsum[blockIdx.x] = incl;
}

__global__ void k_scan2(int nb) {
    __shared__ int sh[512];
    int t = threadIdx.x;
    int v = (t < nb) ? g_bsum[t] : 0;
    sh[t] = v;
    __syncthreads();
    #pragma unroll
    for (int o = 1; o < 512; o <<= 1) {
        int x = sh[t];
        int y = (t >= o) ? sh[t - o] : 0;
        __syncthreads();
        sh[t] = x + y;
        __syncthreads();
    }
    if (t < nb) g_boff[t] = sh[t] - v;
}

__global__ void k_scan3(int n) {
    int i = blockIdx.x * blockDim.x + threadIdx.x;
    if (i >= n) return;
    int off = g_off[i] + g_boff[i >> 8];
    g_off[i] = off;
    g_cur[i] = off;
    g_dinv[i] = rsqrtf((float)(g_cnt[i] + 1));   // +1 self-loop
}

__global__ void k_fill(const void* __restrict__ idxp, int E) {
    int e = blockIdx.x * blockDim.x + threadIdx.x;
    if (e >= E) return;
    int src, dst;
    if (g_is64) {
        const long long* I = (const long long*)idxp;
        src = (int)I[e]; dst = (int)I[E + e];
    } else {
        const int* I = (const int*)idxp;
        src = I[e]; dst = I[E + e];
    }
    int pos = atomicAdd(&g_cur[dst], 1);
    g_srcs[pos] = src;
}

// ---------------- GEMM1: g1[i][j] = dinv[i] * dot(x[i,:], W1[j,:]) ----------------
// 64 rows/block, 8 warps x 8 rows, f32x2 FMAs pairing even/odd k.
// W1p[k2][j] = (W1[j][2k2], W1[j][2k2+1]) so one LDS.128 yields both columns'
// k-pairs already packed in aligned register pairs (zero pack instructions).
__global__ void __launch_bounds__(256) k_gemm1(const float* __restrict__ x,
                                               const float* __restrict__ W1, int n) {
    __shared__ float2 W1p[64 * 64];     // [k2][j]  32KB
    __shared__ float  xs[64][F_IN];     // 32KB
    int tid = threadIdx.x;
    for (int e = tid; e < 64 * 64; e += 256) {
        int k2 = e >> 6, j = e & 63;
        W1p[e] = *(const float2*)(W1 + j * F_IN + 2 * k2);
    }
    int blockRow = blockIdx.x * 64;
    for (int t = tid; t < 64 * 32; t += 256) {
        int r = t >> 5, s = t & 31;
        if (blockRow + r < n)
            ((float4*)xs[r])[s] = ((const float4*)(x + (size_t)(blockRow + r) * F_IN))[s];
    }
    __syncthreads();

    int w = tid >> 5, lane = tid & 31;
    int r0 = w * 8;
    // acc[r][c]: (sum over even k, sum over odd k) for row r0+r, col 2*lane+c
    unsigned long long acc[8][2];
    #pragma unroll
    for (int r = 0; r < 8; r++) { acc[r][0] = 0ull; acc[r][1] = 0ull; }

    #pragma unroll 2
    for (int k2 = 0; k2 < 64; k2++) {
        float4 wv = *(const float4*)(W1p + k2 * 64 + 2 * lane);
        F2U w0, w1;
        w0.f = make_float2(wv.x, wv.y);   // col 2*lane,   k pair
        w1.f = make_float2(wv.z, wv.w);   // col 2*lane+1, k pair
        #pragma unroll
        for (int r = 0; r < 8; r++) {
            F2U xv;
            xv.f = *(const float2*)(xs[r0 + r] + 2 * k2);
            acc[r][0] = fma2(xv.u, w0.u, acc[r][0]);
            acc[r][1] = fma2(xv.u, w1.u, acc[r][1]);
        }
    }
    #pragma unroll
    for (int r = 0; r < 8; r++) {
        int row = blockRow + r0 + r;
        if (row < n) {
            float di = rsqrtf((float)(g_cnt[row] + 1));
            F2U a0, a1;
            a0.u = acc[r][0]; a1.u = acc[r][1];
            float v0 = (a0.f.x + a0.f.y) * di;
            float v1 = (a1.f.x + a1.f.y) * di;
            *(float2*)(g_g1 + (size_t)row * F_H + 2 * lane) = make_float2(v0, v1);
        }
    }
}

// ---------------- gather-reduce layer 1: warp per dst node, unroll 8 ----------------
__global__ void __launch_bounds__(256) k_agg1(int n) {
    int tid = threadIdx.x;
    int w = tid >> 5, lane = tid & 31;
    int i = blockIdx.x * 8 + w;
    if (i >= n) return;
    int start = g_off[i];
    int len = g_cnt[i];
    float2 acc = *(const float2*)(g_g1 + (size_t)i * F_H + 2 * lane);  // self-loop
    for (int base = 0; base < len; base += 32) {
        int m = min(32, len - base);
        int s = (lane < m) ? __ldg(&g_srcs[start + base + lane]) : 0;
        int k = 0;
        for (; k + 8 <= m; k += 8) {
            int ss[8];
            #pragma unroll
            for (int u = 0; u < 8; u++) ss[u] = __shfl_sync(0xffffffffu, s, k + u);
            float2 v[8];
            #pragma unroll
            for (int u = 0; u < 8; u++)
                v[u] = *(const float2*)(g_g1 + (size_t)ss[u] * F_H + 2 * lane);
            #pragma unroll
            for (int u = 0; u < 8; u++) { acc.x += v[u].x; acc.y += v[u].y; }
        }
        for (; k < m; k++) {
            int sk = __shfl_sync(0xffffffffu, s, k);
            float2 v = *(const float2*)(g_g1 + (size_t)sk * F_H + 2 * lane);
            acc.x += v.x; acc.y += v.y;
        }
    }
    *(float2*)(g_acc1 + (size_t)i * F_H + 2 * lane) = acc;
}

// ---------------- fused: finalize1 + ReLU + GEMM2 (4 rows/warp) ----------------
__global__ void __launch_bounds__(256) k_fuse2(const float* __restrict__ b1,
                                               const float* __restrict__ W2, int n) {
    __shared__ float W2t[F_H * F_OUT];  // [j][m]  8KB
    __shared__ float rs[32][F_H];       // 8KB
    int tid = threadIdx.x;
    for (int t = tid; t < F_H * F_OUT; t += 256) {
        int m = t / F_H, j = t % F_H;
        W2t[j * F_OUT + m] = W2[t];
    }
    int blockRow = blockIdx.x * 32;
    for (int t = tid; t < 32 * F_H; t += 256) {
        int r = t >> 6, j = t & 63;
        int row = blockRow + r;
        if (row < n) {
            float di = g_dinv[row];
            rs[r][j] = fmaxf(di * g_acc1[(size_t)row * F_H + j] + b1[j], 0.f);
        }
    }
    __syncthreads();

    int w = tid >> 5, lane = tid & 31;
    int r0 = w * 4;
    float acc[4] = {0.f, 0.f, 0.f, 0.f};
    #pragma unroll 8
    for (int j = 0; j < F_H; j++) {
        float wv = W2t[j * F_OUT + lane];
        #pragma unroll
        for (int r = 0; r < 4; r++) acc[r] += rs[r0 + r][j] * wv;
    }
    #pragma unroll
    for (int r = 0; r < 4; r++) {
        int row = blockRow + r0 + r;
        if (row < n)
            g_g2[(size_t)row * F_OUT + lane] = acc[r] * g_dinv[row];
    }
}

// ---------------- gather-reduce layer 2 + epilogue -> out, unroll 8 ----------------
__global__ void __launch_bounds__(256) k_agg2(const float* __restrict__ b2,
                                              float* __restrict__ out, int n) {
    int tid = threadIdx.x;
    int w = tid >> 5, lane = tid & 31;
    int i = blockIdx.x * 8 + w;
    if (i >= n) return;
    int start = g_off[i];
    int len = g_cnt[i];
    float acc = g_g2[(size_t)i * F_OUT + lane];   // self-loop
    for (int base = 0; base < len; base += 32) {
        int m = min(32, len - base);
        int s = (lane < m) ? __ldg(&g_srcs[start + base + lane]) : 0;
        int k = 0;
        for (; k + 8 <= m; k += 8) {
            int ss[8];
            #pragma unroll
            for (int u = 0; u < 8; u++) ss[u] = __shfl_sync(0xffffffffu, s, k + u);
            float v[8];
            #pragma unroll
            for (int u = 0; u < 8; u++) v[u] = g_g2[(size_t)ss[u] * F_OUT + lane];
            #pragma unroll
            for (int u = 0; u < 8; u++) acc += v[u];
        }
        for (; k < m; k++) {
            int sk = __shfl_sync(0xffffffffu, s, k);
            acc += g_g2[(size_t)sk * F_OUT + lane];
        }
    }
    out[(size_t)i * F_OUT + lane] = g_dinv[i] * acc + b2[lane];
}

// ---------------- launch ----------------
extern "C" void kernel_launch(void* const* d_in, const int* in_sizes, int n_in,
                              void* d_out, int out_size) {
    const float* x  = (const float*)d_in[0];
    const void*  ei = d_in[1];
    const float* W1 = (const float*)d_in[2];
    const float* b1 = (const float*)d_in[3];
    const float* W2 = (const float*)d_in[4];
    const float* b2 = (const float*)d_in[5];
    float* out = (float*)d_out;

    int N = in_sizes[0] / F_IN;       // 100000
    int E = in_sizes[1] / 2;          // 1600000
    if (N > NN) N = NN;
    if (E > EE) E = EE;

    int nB = (N + 255) / 256;         // 391
    int eB = (E + 255) / 256;
    int gemmBlocks = (N + 63) / 64;   // 1563
    int tileBlocks = (N + 31) / 32;   // 3125
    int aggBlocks  = (N + 7) / 8;     // 12500

    k_detzero<<<nB, 256>>>((const unsigned long long*)ei, N);  // 0
    k_count<<<eB, 256>>>(ei, E);                               // 1
    k_scan1<<<nB, 256>>>(N);                                   // 2
    k_gemm1<<<gemmBlocks, 256>>>(x, W1, N);                    // 3  <- profiled slot
    k_scan2<<<1, 512>>>(nB);                                   // 4
    k_scan3<<<nB, 256>>>(N);                                   // 5
    k_fill<<<eB, 256>>>(ei, E);                                // 6
    k_agg1<<<aggBlocks, 256>>>(N);                             // 7
    k_fuse2<<<tileBlocks, 256>>>(b1, W2, N);                   // 8
    k_agg2<<<aggBlocks, 256>>>(b2, out, N);                    // 9
}